// round 16
// baseline (speedup 1.0000x reference)
#include <cuda_runtime.h>

#define BATCH 32
#define NN 18
#define SA_W 24              // padded row width (96 B, float4-aligned)
#define PP 2048
#define EE 150
#define HD 64
#define NB 128
#define NT 512
#define CHUNK 512            // p per phase-1 block
#define NWAIT 32             // blocks that continue past the barrier

// ---- scratch (__device__ globals; no allocation allowed) ----
__device__ __align__(16) float d_Mpart[4 * BATCH * NN * 8]; // per-chunk partial moments
__device__ unsigned int g_cnt_chunk[4] = {0, 0, 0, 0};
__device__ unsigned int g_cnt_top = 0;
__device__ unsigned int g_sense = 0;

// Degree-5 Taylor coeffs (in y) of tanh(a*y + c):  T(w)=w - w^3/3 + (2/15)w^5
__device__ __forceinline__ void build_tanh_poly(float a, float c, float* T) {
    float w1[2] = {c, a};
    float w2[3] = {c * c, 2.f * a * c, a * a};
    float w3[4] = {0, 0, 0, 0};
#pragma unroll
    for (int i = 0; i < 3; i++)
#pragma unroll
        for (int k = 0; k < 2; k++) w3[i + k] += w2[i] * w1[k];
    float w5[6] = {0, 0, 0, 0, 0, 0};
#pragma unroll
    for (int i = 0; i < 4; i++)
#pragma unroll
        for (int k = 0; k < 3; k++) w5[i + k] += w3[i] * w2[k];
#pragma unroll
    for (int j = 0; j < 6; j++) {
        float t = (2.0f / 15.0f) * w5[j];
        if (j < 4) t -= w3[j] * (1.0f / 3.0f);
        if (j < 2) t += w1[j];
        T[j] = t;
    }
}

__global__ void __launch_bounds__(NT, 1) fused_kernel(
    const float* __restrict__ x,   const int* __restrict__ ei,
    const float* __restrict__ att,
    const float* __restrict__ czw, const float* __restrict__ czb,
    const float* __restrict__ chw, const float* __restrict__ chb,
    const float* __restrict__ lzw, const float* __restrict__ lzb,
    const float* __restrict__ lhw, const float* __restrict__ lhb,
    const float* __restrict__ gam, const float* __restrict__ bet,
    const float* __restrict__ f1w, const float* __restrict__ f1b,
    const float* __restrict__ f2w, const float* __restrict__ f2b,
    const float* __restrict__ f3w, const float* __restrict__ f3b,
    float* __restrict__ out)
{
    __shared__ float sdeg[NN], sdinv[NN];
    __shared__ __align__(16) float sA[NN * SA_W];  // padded rows; cols >= NN stay 0
    __shared__ __align__(16) float scoef[HD * 8];
    __shared__ __align__(16) float sq[1280];       // e values [0..512); tail coef scratch
    __shared__ float sC2[49], sS1[7];
    __shared__ float ssc[NN], ssf[NN];
    // union buffer: phase1 sy[18*512]; tail: sM[4032] + sred1/2 + sh + so1 + s2
    __shared__ __align__(16) float ubuf[NN * CHUNK];
    float* sy    = ubuf;
    float* sM    = ubuf;                       // [0..4032)
    float* sred1 = ubuf + 4096;                // 594
    float* sred2 = ubuf + 4800;                // 594
    float* sh    = ubuf + 5504;                // 1152
    float* so1   = ubuf + 6720;                // 64
    float* s2    = ubuf + 6784;                // 32

    int t = threadIdx.x;
    int bid = blockIdx.x;
    int lane = t & 31, w = t >> 5;
    int chunk = bid & 3, b_my = bid >> 2;

    // ---- prefetch x (1 float/thread) and att: hide DRAM latency behind prep ----
    const float* xb = x + (size_t)b_my * NN * PP + chunk * CHUNK + t;
    float xv[NN];
#pragma unroll
    for (int k = 0; k < NN; k++) xv[k] = xb[k * PP];

    // unnormalized weights: e = exp(att) (norm folded into tail via M0 totals)
    sq[t] = __expf(att[chunk * CHUNK + t]);

    // ================= PREP: adjacency (single atomic round, padded rows) =========
    if (t < NN) sdeg[t] = 1.0f;                // self loop contributes 1
    for (int i = t; i < NN * SA_W; i += NT) sA[i] = 0.f;
    __syncthreads();
    if (t < EE) {
        int s = ei[t], d = ei[EE + t];
        atomicAdd(&sdeg[d], 1.0f);
        atomicAdd(&sA[d * SA_W + s], 1.0f);    // raw edge count
    }
    __syncthreads();
    if (t < NN) sdinv[t] = rsqrtf(sdeg[t]);    // deg >= 1 always (self loop)
    __syncthreads();
    for (int i = t; i < NN * SA_W; i += NT) {
        int r = i / SA_W, c = i - r * SA_W;    // r = dst, c = src
        if (c < NN) {
            float v = sA[i] * sdinv[r] * sdinv[c];
            if (r == c) v += sdinv[r] * sdinv[r];  // self loop
            sA[i] = v;
        }
    }
    __syncthreads();

    // ========== PHASE 1: GEMV (vectorized LDS.128) -> shared, warp-per-n moments ==
    {
#pragma unroll
        for (int n = 0; n < NN; n++) {
            const float4* row = (const float4*)(sA + n * SA_W);
            float4 a0 = row[0], a1 = row[1], a2 = row[2], a3 = row[3];
            float y = fmaf(sA[n * SA_W + 16], xv[16], sA[n * SA_W + 17] * xv[17]);
            y = fmaf(a0.x, xv[0], y);  y = fmaf(a0.y, xv[1], y);
            y = fmaf(a0.z, xv[2], y);  y = fmaf(a0.w, xv[3], y);
            y = fmaf(a1.x, xv[4], y);  y = fmaf(a1.y, xv[5], y);
            y = fmaf(a1.z, xv[6], y);  y = fmaf(a1.w, xv[7], y);
            y = fmaf(a2.x, xv[8], y);  y = fmaf(a2.y, xv[9], y);
            y = fmaf(a2.z, xv[10], y); y = fmaf(a2.w, xv[11], y);
            y = fmaf(a3.x, xv[12], y); y = fmaf(a3.y, xv[13], y);
            y = fmaf(a3.z, xv[14], y); y = fmaf(a3.w, xv[15], y);
            sy[n * CHUNK + t] = y;
        }
        __syncthreads();

        // preload q for this lane's 16 p as 4 float4s (reused by both tasks)
        float4 qv[4];
        const float4* sq4 = (const float4*)sq;
#pragma unroll
        for (int i = 0; i < 4; i++) qv[i] = sq4[i * 32 + lane];

        // 18 tasks over 16 warps: warp w does n=w, and n=w+16 for w<2
#pragma unroll
        for (int task = 0; task < 2; task++) {
            int n = w + task * 16;
            if (n < NN) {
                const float4* yn4 = (const float4*)(sy + n * CHUNK);
                float m0 = 0.f, m1 = 0.f, m2 = 0.f, m3 = 0.f, m4 = 0.f, m5 = 0.f, m6 = 0.f;
#pragma unroll
                for (int i = 0; i < 4; i++) {
                    float4 yv = yn4[i * 32 + lane];
                    float y, tt;
                    y = yv.x; tt = qv[i].x; m0 += tt;
                    tt *= y; m1 += tt; tt *= y; m2 += tt; tt *= y; m3 += tt;
                    tt *= y; m4 += tt; tt *= y; m5 += tt; tt *= y; m6 += tt;
                    y = yv.y; tt = qv[i].y; m0 += tt;
                    tt *= y; m1 += tt; tt *= y; m2 += tt; tt *= y; m3 += tt;
                    tt *= y; m4 += tt; tt *= y; m5 += tt; tt *= y; m6 += tt;
                    y = yv.z; tt = qv[i].z; m0 += tt;
                    tt *= y; m1 += tt; tt *= y; m2 += tt; tt *= y; m3 += tt;
                    tt *= y; m4 += tt; tt *= y; m5 += tt; tt *= y; m6 += tt;
                    y = yv.w; tt = qv[i].w; m0 += tt;
                    tt *= y; m1 += tt; tt *= y; m2 += tt; tt *= y; m3 += tt;
                    tt *= y; m4 += tt; tt *= y; m5 += tt; tt *= y; m6 += tt;
                }
#pragma unroll
                for (int o = 16; o; o >>= 1) {
                    m0 += __shfl_down_sync(0xffffffffu, m0, o);
                    m1 += __shfl_down_sync(0xffffffffu, m1, o);
                    m2 += __shfl_down_sync(0xffffffffu, m2, o);
                    m3 += __shfl_down_sync(0xffffffffu, m3, o);
                    m4 += __shfl_down_sync(0xffffffffu, m4, o);
                    m5 += __shfl_down_sync(0xffffffffu, m5, o);
                    m6 += __shfl_down_sync(0xffffffffu, m6, o);
                }
                if (lane == 0) {
                    float* dst = &d_Mpart[((chunk * BATCH + b_my) * NN + n) * 8];
                    dst[0] = m0; dst[1] = m1; dst[2] = m2; dst[3] = m3;
                    dst[4] = m4; dst[5] = m5; dst[6] = m6;
                }
            }
        }
    }

    // ========== hierarchical grid barrier; blocks >= NWAIT arrive & exit ==========
    __syncthreads();
    if (t == 0) {
        __threadfence();
        unsigned int s0 = *(volatile unsigned int*)&g_sense;
        unsigned int my = atomicAdd(&g_cnt_chunk[chunk], 1);
        if (my == BATCH - 1) {                 // last arrival of this chunk
            g_cnt_chunk[chunk] = 0;
            unsigned int m2 = atomicAdd(&g_cnt_top, 1);
            if (m2 == 3) {                     // last chunk overall
                g_cnt_top = 0;
                __threadfence();
                atomicAdd(&g_sense, 1);
            } else if (bid < NWAIT) {
                while (*(volatile unsigned int*)&g_sense == s0) { }
            }
        } else if (bid < NWAIT) {
            while (*(volatile unsigned int*)&g_sense == s0) { }
        }
        __threadfence();
    }
    __syncthreads();
    if (bid >= NWAIT) return;

    int b_blk = bid;

    // normalization: total Σe = sum over chunks of M0 at (b=0, n=0)
    float inv_q;
    {
        float tot = d_Mpart[0] + d_Mpart[1 * BATCH * NN * 8]
                  + d_Mpart[2 * BATCH * NN * 8] + d_Mpart[3 * BATCH * NN * 8];
        inv_q = 0.5f / tot;
    }

    // ---- TAIL, overlapped: warps 0-7 reduce d_Mpart -> sM (scaled); warps 8-15 coef ----
    if (t < 256) {
        for (int i = t; i < BATCH * NN * 7; i += 256) {
            int b = i / 126;
            int rem = i - b * 126;
            int n = rem / 7, j = rem - n * 7;
            float s = 0.f;
#pragma unroll
            for (int ck = 0; ck < 4; ck++)
                s += d_Mpart[((ck * BATCH + b) * NN + n) * 8 + j];
            sM[i] = s * inv_q;
        }
    } else {
        int t2 = t - 256;                      // 0..255
        // stage conv vectors into sq[1024..1280): [czw|czb|chw|chb]
        {
            int which = t2 >> 6, idx = t2 & 63;
            float v = (which == 0) ? czw[idx] : (which == 1) ? czb[idx]
                    : (which == 2) ? chw[idx] : chb[idx];
            sq[1024 + t2] = v;
        }
        asm volatile("bar.sync 1, 256;" ::: "memory");
        // partial dots: channel c = t2>>2, quarter qq = t2&3 (16 k each)
        {
            int c = t2 >> 2, qq = t2 & 3;
            const float* cv = sq + 1024;
            float paz = 0.f, pcz = 0.f, pah = 0.f, pch = 0.f;
#pragma unroll
            for (int i = 0; i < 16; i++) {
                int k = qq * 16 + i;
                float wz = lzw[c * 2 * HD + k];
                float wh = lhw[c * 2 * HD + k];
                paz = fmaf(wz, cv[k], paz);
                pcz = fmaf(wz, cv[64 + k], pcz);
                pah = fmaf(wh, cv[128 + k], pah);
                pch = fmaf(wh, cv[192 + k], pch);
            }
            sq[t2] = paz; sq[256 + t2] = pcz; sq[512 + t2] = pah; sq[768 + t2] = pch;
        }
        asm volatile("bar.sync 1, 256;" ::: "memory");
        if (t2 < HD) {
            float az = sq[4 * t2] + sq[4 * t2 + 1] + sq[4 * t2 + 2] + sq[4 * t2 + 3];
            float cz = sq[256 + 4 * t2] + sq[256 + 4 * t2 + 1] + sq[256 + 4 * t2 + 2] + sq[256 + 4 * t2 + 3];
            float ah = sq[512 + 4 * t2] + sq[512 + 4 * t2 + 1] + sq[512 + 4 * t2 + 2] + sq[512 + 4 * t2 + 3];
            float ch = sq[768 + 4 * t2] + sq[768 + 4 * t2 + 1] + sq[768 + 4 * t2 + 2] + sq[768 + 4 * t2 + 3];
            float Tv[6], Tu[6];
            build_tanh_poly(ah, ch + lhb[t2], Tv);
            build_tanh_poly(-0.5f * az, -0.5f * (cz + lzb[t2]), Tu);
            float G[7];
#pragma unroll
            for (int j = 0; j < 7; j++) G[j] = (j < 6) ? Tv[j] : 0.f;
#pragma unroll
            for (int i = 0; i < 6; i++)
#pragma unroll
                for (int k = 0; k < 6; k++)
                    if (i + k <= 6) G[i + k] += Tv[i] * Tu[k];
#pragma unroll
            for (int j = 0; j < 7; j++) scoef[t2 * 8 + j] = G[j];
            scoef[t2 * 8 + 7] = 0.f;
        }
    }
    __syncthreads();

    // ---- coef Gramians for BN stats ----
    if (t < 49) {
        int j = t / 7, jp = t - j * 7;
        float s = 0.f;
#pragma unroll 8
        for (int c = 0; c < HD; c++)
            s = fmaf(scoef[c * 8 + j], scoef[c * 8 + jp], s);
        sC2[t] = s;
    } else if (t >= 64 && t < 71) {
        int j = t - 64;
        float s = 0.f;
#pragma unroll 8
        for (int c = 0; c < HD; c++) s += scoef[c * 8 + j];
        sS1[j] = s;
    }
    __syncthreads();

    // ---- BN stats from M (redundant per block, cheap) ----
    for (int idx = t; idx < NN * BATCH; idx += NT) {
        int n = idx >> 5, b = idx & 31;
        float m[7];
#pragma unroll
        for (int j = 0; j < 7; j++) m[j] = sM[b * 126 + n * 7 + j];
        float mp = 0.f;
#pragma unroll
        for (int j = 0; j < 7; j++) mp = fmaf(sS1[j], m[j], mp);
        float vp = 0.f;
#pragma unroll
        for (int j = 0; j < 7; j++) {
            float wj = 0.f;
#pragma unroll
            for (int jp = 0; jp < 7; jp++) wj = fmaf(sC2[j * 7 + jp], m[jp], wj);
            vp = fmaf(m[j], wj, vp);
        }
        sred1[n * 33 + b] = mp;
        sred2[n * 33 + b] = vp;
    }
    __syncthreads();
    if (t < NN) {
        float s1 = 0.f, s2v = 0.f;
#pragma unroll
        for (int b = 0; b < BATCH; b++) {
            s1 += sred1[t * 33 + b];
            s2v += sred2[t * 33 + b];
        }
        float mean = s1 * (1.0f / 2048.f);
        float ex2 = s2v * (1.0f / 2048.f);
        float var = ex2 - mean * mean;
        float rstd = rsqrtf(var + 1e-5f);
        float sc = gam[t] * rstd;
        ssc[t] = sc;
        ssf[t] = bet[t] - mean * sc;
    }
    __syncthreads();

    // ---- h[b_blk] (normalized + lrelu) into shared ----
    for (int idx = t; idx < NN * HD; idx += NT) {
        int n = idx >> 6, c = idx & 63;
        float raw = 0.f;
        const float* mb = sM + b_blk * 126 + n * 7;
#pragma unroll
        for (int j = 0; j < 7; j++) raw = fmaf(scoef[c * 8 + j], mb[j], raw);
        float g = fmaf(raw, ssc[n], ssf[n]);
        g = g > 0.f ? g : 0.01f * g;
        sh[idx] = g;
    }
    __syncthreads();

    // ---- fc1: warp w handles o = w*4 .. w*4+3 ----
    {
        const float4* sh4 = (const float4*)sh;
#pragma unroll
        for (int i = 0; i < 4; i++) {
            int o = w * 4 + i;
            const float4* w4 = (const float4*)(f1w + (size_t)o * NN * HD);
            float acc = 0.f;
#pragma unroll
            for (int it = 0; it < 9; it++) {
                int i4 = it * 32 + lane;
                float4 hv = sh4[i4];
                float4 wv = w4[i4];
                acc = fmaf(hv.x, wv.x, acc);
                acc = fmaf(hv.y, wv.y, acc);
                acc = fmaf(hv.z, wv.z, acc);
                acc = fmaf(hv.w, wv.w, acc);
            }
#pragma unroll
            for (int oo = 16; oo; oo >>= 1) acc += __shfl_down_sync(0xffffffffu, acc, oo);
            if (lane == 0) {
                float s = acc + f1b[o];
                so1[o] = s > 0.f ? s : 0.01f * s;
            }
        }
    }
    __syncthreads();

    // ---- fc2 (+lrelu) ----
    if (t < 32) {
        float acc = f2b[t];
        const float* wrow = f2w + t * HD;
#pragma unroll
        for (int k = 0; k < HD; k++) acc = fmaf(so1[k], wrow[k], acc);
        s2[t] = acc > 0.f ? acc : 0.01f * acc;
    }
    __syncthreads();

    // ---- fc3 ----
    if (t == 0) {
        float s = f3b[0];
#pragma unroll
        for (int k = 0; k < 32; k++) s = fmaf(s2[k], f3w[k], s);
        out[b_blk] = s;
    }
}

// ============================================================
extern "C" void kernel_launch(void* const* d_in, const int* in_sizes, int n_in,
                              void* d_out, int out_size)
{
    const float* x    = (const float*)d_in[0];
    const int*   ei   = (const int*)  d_in[1];
    const float* att  = (const float*)d_in[2];
    const float* czw  = (const float*)d_in[3];
    const float* czb  = (const float*)d_in[4];
    const float* chw  = (const float*)d_in[5];
    const float* chb  = (const float*)d_in[6];
    const float* lzw  = (const float*)d_in[7];
    const float* lzb  = (const float*)d_in[8];
    const float* lhw  = (const float*)d_in[9];
    const float* lhb  = (const float*)d_in[10];
    const float* gam  = (const float*)d_in[11];
    const float* bet  = (const float*)d_in[12];
    const float* f1w  = (const float*)d_in[13];
    const float* f1b  = (const float*)d_in[14];
    const float* f2w  = (const float*)d_in[15];
    const float* f2b  = (const float*)d_in[16];
    const float* f3w  = (const float*)d_in[17];
    const float* f3b  = (const float*)d_in[18];

    fused_kernel<<<NB, NT>>>(x, ei, att, czw, czb, chw, chb, lzw, lzb, lhw, lhb,
                             gam, bet, f1w, f1b, f2w, f2b, f3w, f3b, (float*)d_out);
}